// round 9
// baseline (speedup 1.0000x reference)
#include <cuda_runtime.h>
#include <cuda_fp16.h>
#include <cstdint>

#define BB 4
#define CK 64
#define NKEY 8192
#define MQ 1024
#define CVAL 512
#define BM 32
#define CHUNK 64
#define NCH (NKEY/CHUNK)
#define NT 512
#define SHIFT 10.0f

__device__ __half g_kth[(size_t)BB*NKEY*CK];   // [b][n][c] hi
__device__ __half g_ktl[(size_t)BB*NKEY*CK];   // [b][n][c] lo
__device__ __half g_qth[(size_t)BB*CK*MQ];     // [b][c][m] hi
__device__ __half g_qtl[(size_t)BB*CK*MQ];     // [b][c][m] lo
__device__ __half g_vhi[(size_t)BB*CVAL*NKEY]; // [b][c][n] hi
__device__ float  g_asq[BB*NKEY];
__device__ float  g_qsq[BB*MQ];

// smem byte offsets
#define SM_ASQ 0        /* 2*256 */
#define SM_QSQ 512
#define SM_INV 640
#define SM_SE  768
#define SM_QH  1024     /* 64 rows * 80B */
#define SM_QL  6144
#define SM_PH  11264    /* 64 rows * 80B */
#define SM_KH  16384    /* 2 * 64*128 */
#define SM_KL  32768
#define SM_V   49152    /* 2 * 512*128 */
#define SMEM_BYTES 180224

__device__ __forceinline__ uint32_t smem_u32(const void* p){
    uint32_t a;
    asm("{ .reg .u64 t; cvta.to.shared.u64 t, %1; cvt.u32.u64 %0, t; }":"=r"(a):"l"(p));
    return a;
}
__device__ __forceinline__ void cpa16(uint32_t s, const void* g){
    asm volatile("cp.async.cg.shared.global [%0], [%1], 16;"::"r"(s),"l"(g):"memory");
}
#define CP_COMMIT asm volatile("cp.async.commit_group;":::"memory")
#define CP_WAIT0  asm volatile("cp.async.wait_group 0;":::"memory")

__device__ __forceinline__ uint32_t swz(uint32_t o){ return o ^ ((o>>3)&0x70); }

__device__ __forceinline__ void ldsm4(uint32_t a, uint32_t* r){
    asm volatile("ldmatrix.sync.aligned.m8n8.x4.shared.b16 {%0,%1,%2,%3}, [%4];"
        :"=r"(r[0]),"=r"(r[1]),"=r"(r[2]),"=r"(r[3]):"r"(a));
}
__device__ __forceinline__ void ldsm4t(uint32_t a, uint32_t* r){
    asm volatile("ldmatrix.sync.aligned.m8n8.x4.trans.shared.b16 {%0,%1,%2,%3}, [%4];"
        :"=r"(r[0]),"=r"(r[1]),"=r"(r[2]),"=r"(r[3]):"r"(a));
}
__device__ __forceinline__ void mmaf16(float* d, const uint32_t* a, const uint32_t* b){
    asm volatile("mma.sync.aligned.m16n8k16.row.col.f32.f16.f16.f32 "
        "{%0,%1,%2,%3},{%4,%5,%6,%7},{%8,%9},{%0,%1,%2,%3};"
        :"+f"(d[0]),"+f"(d[1]),"+f"(d[2]),"+f"(d[3])
        :"r"(a[0]),"r"(a[1]),"r"(a[2]),"r"(a[3]),"r"(b[0]),"r"(b[1]));
}
__device__ __forceinline__ uint32_t a_addr(uint32_t base, int rowbase, int kbyte, int lane){
    int r = rowbase + (lane&7) + ((lane>>3)&1)*8;
    uint32_t off = (uint32_t)(r*128 + kbyte + ((lane>>4)<<4));
    return base + swz(off);
}
__device__ __forceinline__ uint32_t b_addr(uint32_t base, int kbase, int nbase, int lane){
    int kk = kbase + (lane&7) + ((lane>>3)&1)*8;
    int nn = nbase + ((lane>>4)<<3);
    return base + (uint32_t)(kk*80 + nn*2);
}

// ---------------- fused prep (block-range dispatch) ----------------
#define VPREP_BLKS 16384
#define KPREP_BLKS 128
#define QPREP_BLKS 1024
#define QSQK_BLKS  16
#define PREP_BLKS (VPREP_BLKS + KPREP_BLKS + QPREP_BLKS + QSQK_BLKS)

__global__ void prep(const float* __restrict__ mk, const float* __restrict__ qk,
                     const float* __restrict__ mv){
    int blk = blockIdx.x;
    if (blk < VPREP_BLKS){
        size_t base = ((size_t)blk*256 + threadIdx.x)*4;
        float4 v = *(const float4*)(mv + base);
        *(__half2*)(g_vhi+base)   = __halves2half2(__float2half_rn(v.x), __float2half_rn(v.y));
        *(__half2*)(g_vhi+base+2) = __halves2half2(__float2half_rn(v.z), __float2half_rn(v.w));
        return;
    }
    blk -= VPREP_BLKS;
    if (blk < KPREP_BLKS){
        int i = blk*256 + threadIdx.x;
        int b = i>>13, n = i&(NKEY-1);
        const float* p = mk + ((size_t)b*CK)*NKEY + n;
        __half* oh = g_kth + ((size_t)b*NKEY + n)*CK;
        __half* ol = g_ktl + ((size_t)b*NKEY + n)*CK;
        float s = 0.f;
#pragma unroll 8
        for (int c = 0; c < CK; ++c){
            float v = p[(size_t)c*NKEY];
            s = fmaf(v, v, s);
            __half h = __float2half_rn(v);
            oh[c] = h; ol[c] = __float2half_rn(v - __half2float(h));
        }
        g_asq[i] = s;
        return;
    }
    blk -= KPREP_BLKS;
    if (blk < QPREP_BLKS){
        int i = blk*256 + threadIdx.x;
        float v = qk[i];
        __half h = __float2half_rn(v);
        g_qth[i] = h; g_qtl[i] = __float2half_rn(v - __half2float(h));
        return;
    }
    blk -= QPREP_BLKS;
    {
        int i = blk*256 + threadIdx.x;
        int b = i>>10, m = i&(MQ-1);
        float s = 0.f;
#pragma unroll 8
        for (int c = 0; c < CK; ++c){ float v = qk[((size_t)b*CK+c)*MQ + m]; s = fmaf(v,v,s); }
        g_qsq[i] = s;
    }
}

// ---------------- main ----------------
__global__ void __launch_bounds__(NT,1) mr_hmma(float* __restrict__ out){
    extern __shared__ char smc[];
    float* smf = (float*)smc;
    const uint32_t sb = smem_u32(smc);
    const int tid = threadIdx.x, wid = tid>>5, lane = tid&31;
    const int b = blockIdx.y, m0 = blockIdx.x*BM;
    const int g = lane>>2, tg = lane&3;
    const int wn = wid&3, wm = wid>>2;       // QK job: n16-tile wn, m8-tile wm

    if (tid < 32) smf[SM_SE/4 + tid] = 0.f;
    if (tid < 256){
        int c = tid>>2, sg = tid&3;
        size_t qo = ((size_t)b*CK + c)*MQ + m0 + sg*8;
        cpa16(sb + SM_QH + c*80 + sg*16, g_qth + qo);
        cpa16(sb + SM_QL + c*80 + sg*16, g_qtl + qo);
        if (tid < 8) cpa16(sb + SM_QSQ + tid*16, g_qsq + b*MQ + m0 + tid*4);
    }
#define PREFETCH(n0, bf) do {                                                   \
    {                                                                           \
        int n = tid>>3, sg = tid&7;                                             \
        size_t ko = ((size_t)b*NKEY + (n0) + n)*CK + sg*8;                      \
        cpa16(sb + SM_KH + (bf)*8192 + swz(n*128 + sg*16), g_kth + ko);         \
        cpa16(sb + SM_KL + (bf)*8192 + swz(n*128 + sg*16), g_ktl + ko);         \
    }                                                                           \
    _Pragma("unroll")                                                           \
    for (int k2 = 0; k2 < 8; ++k2){                                             \
        int i = tid + k2*NT, c = i>>3, sg = i&7;                                \
        cpa16(sb + SM_V + (bf)*65536 + swz(c*128 + sg*16),                      \
              g_vhi + ((size_t)b*CVAL + c)*NKEY + (n0) + sg*8);                 \
    }                                                                           \
    if (tid < 16) cpa16(sb + SM_ASQ + (bf)*256 + tid*16,                        \
                        g_asq + b*NKEY + (n0) + tid*4);                         \
    CP_COMMIT;                                                                  \
} while (0)

    PREFETCH(0, 0);
    CP_WAIT0;
    __syncthreads();

    // ---- hoist Q fragments (iteration-invariant): m8 slice for this warp ----
    uint32_t qh[4][2], ql[4][2];
    {
        const int nb = (wm>>1)*16, sel = (wm&1)*2;
#pragma unroll
        for (int ks = 0; ks < 4; ++ks){
            uint32_t t4[4];
            ldsm4t(b_addr(sb + SM_QH, ks*16, nb, lane), t4);
            qh[ks][0] = t4[sel]; qh[ks][1] = t4[sel+1];
            ldsm4t(b_addr(sb + SM_QL, ks*16, nb, lane), t4);
            ql[ks][0] = t4[sel]; ql[ks][1] = t4[sel+1];
        }
    }

    float pacc[2][4][4];
#pragma unroll
    for (int i = 0; i < 2; ++i)
#pragma unroll
        for (int j = 0; j < 4; ++j)
#pragma unroll
            for (int k = 0; k < 4; ++k) pacc[i][j][k] = 0.f;
    float se[2] = {0.f, 0.f};

    for (int it = 0; it < NCH; ++it){
        const int buf = it & 1;
        const uint32_t KHb = sb + SM_KH + buf*8192;
        const uint32_t KLb = sb + SM_KL + buf*8192;
        const uint32_t Vb  = sb + SM_V  + buf*65536;
        const float* ASQb = smf + SM_ASQ/4 + buf*64;

        if (it + 1 < NCH) PREFETCH((it+1)*CHUNK, buf^1);

        // ---- QK: warp computes S tile n16 x m8, 3 split passes ----
        float sacc[4] = {0,0,0,0};
#pragma unroll
        for (int ks = 0; ks < 4; ++ks){
            uint32_t ah[4], al[4];
            ldsm4(a_addr(KHb, wn*16, ks*32, lane), ah);
            ldsm4(a_addr(KLb, wn*16, ks*32, lane), al);
            mmaf16(sacc, ah, qh[ks]);
            mmaf16(sacc, ah, ql[ks]);
            mmaf16(sacc, al, qh[ks]);
        }

        // ---- epilogue: exp (re-centered) + P stores + sumexp ----
        {
            float as0 = ASQb[wn*16 + g], as1 = ASQb[wn*16 + g + 8];
            int m = wm*8 + tg*2;
            float q0 = smf[SM_QSQ/4 + m], q1 = smf[SM_QSQ/4 + m + 1];
            float p00 = __expf((2.f*sacc[0] - as0 - q0)*0.125f + SHIFT);
            float p01 = __expf((2.f*sacc[1] - as0 - q1)*0.125f + SHIFT);
            float p10 = __expf((2.f*sacc[2] - as1 - q0)*0.125f + SHIFT);
            float p11 = __expf((2.f*sacc[3] - as1 - q1)*0.125f + SHIFT);
            se[0] += p00 + p10;
            se[1] += p01 + p11;
            int r0 = wn*16 + g, r1 = r0 + 8;
            *(__half2*)(smc + SM_PH + r0*80 + m*2) =
                __halves2half2(__float2half_rn(p00), __float2half_rn(p01));
            *(__half2*)(smc + SM_PH + r1*80 + m*2) =
                __halves2half2(__float2half_rn(p10), __float2half_rn(p11));
        }
        __syncthreads();

        // ---- PV: warp owns 32 c-rows; acc += V * Ph over m32 ----
#pragma unroll
        for (int ks = 0; ks < 4; ++ks){
            uint32_t va[2][4], bh[2][4];
#pragma unroll
            for (int ct = 0; ct < 2; ++ct)
                ldsm4(a_addr(Vb, wid*32 + ct*16, ks*32, lane), va[ct]);
#pragma unroll
            for (int mh = 0; mh < 2; ++mh)
                ldsm4t(b_addr(sb + SM_PH, ks*16, mh*16, lane), bh[mh]);
#pragma unroll
            for (int ct = 0; ct < 2; ++ct)
#pragma unroll
                for (int mt = 0; mt < 4; ++mt)
                    mmaf16(pacc[ct][mt], va[ct], &bh[mt>>1][(mt&1)*2]);
        }

        CP_WAIT0;
        __syncthreads();
    }

    // ---- sumexp reduce ----
#pragma unroll
    for (int c = 0; c < 2; ++c){
        float v = se[c];
        v += __shfl_xor_sync(0xffffffffu, v, 4);
        v += __shfl_xor_sync(0xffffffffu, v, 8);
        v += __shfl_xor_sync(0xffffffffu, v, 16);
        if (g == 0) atomicAdd(smf + SM_SE/4 + wm*8 + tg*2 + c, v);
    }
    __syncthreads();
    if (tid < 32) smf[SM_INV/4 + tid] = 1.f / smf[SM_SE/4 + tid];
    __syncthreads();

    // ---- writeout ----
#pragma unroll
    for (int ct = 0; ct < 2; ++ct){
        int c = wid*32 + ct*16 + g;
        float* po0 = out + ((size_t)(b*CVAL + c))*MQ + m0;
        float* po1 = po0 + 8*MQ;
#pragma unroll
        for (int mt = 0; mt < 4; ++mt){
            int m = mt*8 + tg*2;
            float i0 = smf[SM_INV/4 + m], i1 = smf[SM_INV/4 + m + 1];
            float2 o0 = { pacc[ct][mt][0]*i0, pacc[ct][mt][1]*i1 };
            float2 o1 = { pacc[ct][mt][2]*i0, pacc[ct][mt][3]*i1 };
            *(float2*)(po0 + m) = o0;
            *(float2*)(po1 + m) = o1;
        }
    }
}

extern "C" void kernel_launch(void* const* d_in, const int* in_sizes, int n_in,
                              void* d_out, int out_size){
    const float* mk = (const float*)d_in[0];
    const float* qk = (const float*)d_in[1];
    const float* mv = (const float*)d_in[2];
    float* out = (float*)d_out;

    prep<<<PREP_BLKS, 256>>>(mk, qk, mv);

    cudaFuncSetAttribute(mr_hmma, cudaFuncAttributeMaxDynamicSharedMemorySize, SMEM_BYTES);
    dim3 grid(MQ/BM, BB);
    mr_hmma<<<grid, NT, SMEM_BYTES>>>(out);
}

// round 10
// speedup vs baseline: 1.2489x; 1.2489x over previous
#include <cuda_runtime.h>
#include <cuda_fp16.h>
#include <cstdint>

#define BB 4
#define CK 64
#define NKEY 8192
#define MQ 1024
#define CVAL 512
#define BM 32
#define CHUNK 64
#define NCH (NKEY/CHUNK)
#define NT 512
#define SHIFT 10.0f

__device__ __half g_kth[(size_t)BB*NKEY*CK];   // [b][n][c] hi
__device__ __half g_ktl[(size_t)BB*NKEY*CK];   // [b][n][c] lo
__device__ __half g_qth[(size_t)BB*CK*MQ];     // [b][c][m] hi
__device__ __half g_qtl[(size_t)BB*CK*MQ];     // [b][c][m] lo
__device__ __half g_vhi[(size_t)BB*CVAL*NKEY]; // [b][c][n] hi
__device__ float  g_asq[BB*NKEY];
__device__ float  g_qsq[BB*MQ];

// smem byte offsets
#define SM_ASQ 0        /* 2*256 */
#define SM_QSQ 512
#define SM_INV 640
#define SM_SE  768
#define SM_QH  1024     /* 64 rows * 80B */
#define SM_QL  6144
#define SM_PH  11264    /* 64 rows * 80B */
#define SM_KH  16384    /* 2 * 64*128 */
#define SM_KL  32768
#define SM_V   49152    /* 2 * 512*128 */
#define SMEM_BYTES 180224

__device__ __forceinline__ uint32_t smem_u32(const void* p){
    uint32_t a;
    asm("{ .reg .u64 t; cvta.to.shared.u64 t, %1; cvt.u32.u64 %0, t; }":"=r"(a):"l"(p));
    return a;
}
__device__ __forceinline__ void cpa16(uint32_t s, const void* g){
    asm volatile("cp.async.cg.shared.global [%0], [%1], 16;"::"r"(s),"l"(g):"memory");
}
#define CP_COMMIT asm volatile("cp.async.commit_group;":::"memory")
#define CP_WAIT0  asm volatile("cp.async.wait_group 0;":::"memory")

__device__ __forceinline__ uint32_t swz(uint32_t o){ return o ^ ((o>>3)&0x70); }

__device__ __forceinline__ void ldsm4(uint32_t a, uint32_t* r){
    asm volatile("ldmatrix.sync.aligned.m8n8.x4.shared.b16 {%0,%1,%2,%3}, [%4];"
        :"=r"(r[0]),"=r"(r[1]),"=r"(r[2]),"=r"(r[3]):"r"(a));
}
__device__ __forceinline__ void ldsm4t(uint32_t a, uint32_t* r){
    asm volatile("ldmatrix.sync.aligned.m8n8.x4.trans.shared.b16 {%0,%1,%2,%3}, [%4];"
        :"=r"(r[0]),"=r"(r[1]),"=r"(r[2]),"=r"(r[3]):"r"(a));
}
__device__ __forceinline__ void mmaf16(float* d, const uint32_t* a, const uint32_t* b){
    asm volatile("mma.sync.aligned.m16n8k16.row.col.f32.f16.f16.f32 "
        "{%0,%1,%2,%3},{%4,%5,%6,%7},{%8,%9},{%0,%1,%2,%3};"
        :"+f"(d[0]),"+f"(d[1]),"+f"(d[2]),"+f"(d[3])
        :"r"(a[0]),"r"(a[1]),"r"(a[2]),"r"(a[3]),"r"(b[0]),"r"(b[1]));
}
__device__ __forceinline__ uint32_t a_addr(uint32_t base, int rowbase, int kbyte, int lane){
    int r = rowbase + (lane&7) + ((lane>>3)&1)*8;
    uint32_t off = (uint32_t)(r*128 + kbyte + ((lane>>4)<<4));
    return base + swz(off);
}
__device__ __forceinline__ uint32_t b_addr(uint32_t base, int kbase, int nbase, int lane){
    int kk = kbase + (lane&7) + ((lane>>3)&1)*8;
    int nn = nbase + ((lane>>4)<<3);
    return base + (uint32_t)(kk*80 + nn*2);
}

// ---------------- prep (separate kernels — measured-good) ----------------
__global__ void kprep(const float* __restrict__ mk){
    int i = blockIdx.x*blockDim.x + threadIdx.x;
    if (i >= BB*NKEY) return;
    int b = i>>13, n = i&(NKEY-1);
    const float* p = mk + ((size_t)b*CK)*NKEY + n;
    __half* oh = g_kth + ((size_t)b*NKEY + n)*CK;
    __half* ol = g_ktl + ((size_t)b*NKEY + n)*CK;
    float s = 0.f;
#pragma unroll 8
    for (int c = 0; c < CK; ++c){
        float v = p[(size_t)c*NKEY];
        s = fmaf(v, v, s);
        __half h = __float2half_rn(v);
        oh[c] = h; ol[c] = __float2half_rn(v - __half2float(h));
    }
    g_asq[i] = s;
}
__global__ void qprep(const float* __restrict__ qk){
    int i = blockIdx.x*blockDim.x + threadIdx.x;
    if (i >= BB*CK*MQ) return;
    float v = qk[i];
    __half h = __float2half_rn(v);
    g_qth[i] = h; g_qtl[i] = __float2half_rn(v - __half2float(h));
}
__global__ void qsqk(const float* __restrict__ qk){
    int i = blockIdx.x*blockDim.x + threadIdx.x;
    if (i >= BB*MQ) return;
    int b = i>>10, m = i&(MQ-1);
    float s = 0.f;
#pragma unroll 8
    for (int c = 0; c < CK; ++c){ float v = qk[((size_t)b*CK+c)*MQ + m]; s = fmaf(v,v,s); }
    g_qsq[i] = s;
}
__global__ void vprep(const float* __restrict__ mv){
    size_t base = ((size_t)blockIdx.x*blockDim.x + threadIdx.x)*4;
    if (base >= (size_t)BB*CVAL*NKEY) return;
    float4 v = *(const float4*)(mv + base);
    *(__half2*)(g_vhi+base)   = __halves2half2(__float2half_rn(v.x), __float2half_rn(v.y));
    *(__half2*)(g_vhi+base+2) = __halves2half2(__float2half_rn(v.z), __float2half_rn(v.w));
}

// ---------------- main ----------------
__global__ void __launch_bounds__(NT,1) mr_hmma(float* __restrict__ out){
    extern __shared__ char smc[];
    float* smf = (float*)smc;
    const uint32_t sb = smem_u32(smc);
    const int tid = threadIdx.x, wid = tid>>5, lane = tid&31;
    const int b = blockIdx.y, m0 = blockIdx.x*BM;
    const int g = lane>>2, tg = lane&3;
    const int wn = wid&3, wm = wid>>2;       // QK job: n16-tile wn, m8-tile wm

    if (tid < 32) smf[SM_SE/4 + tid] = 0.f;
    if (tid < 256){
        int c = tid>>2, sg = tid&3;
        size_t qo = ((size_t)b*CK + c)*MQ + m0 + sg*8;
        cpa16(sb + SM_QH + c*80 + sg*16, g_qth + qo);
        cpa16(sb + SM_QL + c*80 + sg*16, g_qtl + qo);
        if (tid < 8) cpa16(sb + SM_QSQ + tid*16, g_qsq + b*MQ + m0 + tid*4);
    }
#define PREFETCH(n0, bf) do {                                                   \
    {                                                                           \
        int n = tid>>3, sg = tid&7;                                             \
        size_t ko = ((size_t)b*NKEY + (n0) + n)*CK + sg*8;                      \
        cpa16(sb + SM_KH + (bf)*8192 + swz(n*128 + sg*16), g_kth + ko);         \
        cpa16(sb + SM_KL + (bf)*8192 + swz(n*128 + sg*16), g_ktl + ko);         \
    }                                                                           \
    _Pragma("unroll")                                                           \
    for (int k2 = 0; k2 < 8; ++k2){                                             \
        int i = tid + k2*NT, c = i>>3, sg = i&7;                                \
        cpa16(sb + SM_V + (bf)*65536 + swz(c*128 + sg*16),                      \
              g_vhi + ((size_t)b*CVAL + c)*NKEY + (n0) + sg*8);                 \
    }                                                                           \
    if (tid < 16) cpa16(sb + SM_ASQ + (bf)*256 + tid*16,                        \
                        g_asq + b*NKEY + (n0) + tid*4);                         \
    CP_COMMIT;                                                                  \
} while (0)

    PREFETCH(0, 0);
    CP_WAIT0;
    __syncthreads();

    // ---- hoist Q fragments (iteration-invariant): m8 slice for this warp ----
    uint32_t qh[4][2], ql[4][2];
    {
        const int nb = (wm>>1)*16, sel = (wm&1)*2;
#pragma unroll
        for (int ks = 0; ks < 4; ++ks){
            uint32_t t4[4];
            ldsm4t(b_addr(sb + SM_QH, ks*16, nb, lane), t4);
            qh[ks][0] = t4[sel]; qh[ks][1] = t4[sel+1];
            ldsm4t(b_addr(sb + SM_QL, ks*16, nb, lane), t4);
            ql[ks][0] = t4[sel]; ql[ks][1] = t4[sel+1];
        }
    }
    // hoisted epilogue constants: -qsq*0.125 + SHIFT for this thread's two m cols
    const int mcol = wm*8 + tg*2;
    const float qc0 = -smf[SM_QSQ/4 + mcol]     * 0.125f + SHIFT;
    const float qc1 = -smf[SM_QSQ/4 + mcol + 1] * 0.125f + SHIFT;

    float pacc[2][4][4];
#pragma unroll
    for (int i = 0; i < 2; ++i)
#pragma unroll
        for (int j = 0; j < 4; ++j)
#pragma unroll
            for (int k = 0; k < 4; ++k) pacc[i][j][k] = 0.f;
    float se[2] = {0.f, 0.f};

    for (int it = 0; it < NCH; ++it){
        const int buf = it & 1;
        const uint32_t KHb = sb + SM_KH + buf*8192;
        const uint32_t KLb = sb + SM_KL + buf*8192;
        const uint32_t Vb  = sb + SM_V  + buf*65536;
        const float* ASQb = smf + SM_ASQ/4 + buf*64;

        if (it + 1 < NCH) PREFETCH((it+1)*CHUNK, buf^1);

        // ---- QK: warp computes S tile n16 x m8, 3 split passes ----
        float sacc[4] = {0,0,0,0};
#pragma unroll
        for (int ks = 0; ks < 4; ++ks){
            uint32_t ah[4], al[4];
            ldsm4(a_addr(KHb, wn*16, ks*32, lane), ah);
            ldsm4(a_addr(KLb, wn*16, ks*32, lane), al);
            mmaf16(sacc, ah, qh[ks]);
            mmaf16(sacc, ah, ql[ks]);
            mmaf16(sacc, al, qh[ks]);
        }

        // ---- epilogue: exp (re-centered) + P stores + sumexp ----
        {
            float as0 = ASQb[wn*16 + g]*0.125f, as1 = ASQb[wn*16 + g + 8]*0.125f;
            float p00 = __expf(fmaf(sacc[0], 0.25f, qc0 - as0));
            float p01 = __expf(fmaf(sacc[1], 0.25f, qc1 - as0));
            float p10 = __expf(fmaf(sacc[2], 0.25f, qc0 - as1));
            float p11 = __expf(fmaf(sacc[3], 0.25f, qc1 - as1));
            se[0] += p00 + p10;
            se[1] += p01 + p11;
            int r0 = wn*16 + g, r1 = r0 + 8;
            *(__half2*)(smc + SM_PH + r0*80 + mcol*2) =
                __halves2half2(__float2half_rn(p00), __float2half_rn(p01));
            *(__half2*)(smc + SM_PH + r1*80 + mcol*2) =
                __halves2half2(__float2half_rn(p10), __float2half_rn(p11));
        }
        __syncthreads();

        // ---- PV: warp owns 32 c-rows; acc += V * Ph over m32 ----
#pragma unroll
        for (int ks = 0; ks < 4; ++ks){
            uint32_t va[2][4], bh[2][4];
#pragma unroll
            for (int ct = 0; ct < 2; ++ct)
                ldsm4(a_addr(Vb, wid*32 + ct*16, ks*32, lane), va[ct]);
#pragma unroll
            for (int mh = 0; mh < 2; ++mh)
                ldsm4t(b_addr(sb + SM_PH, ks*16, mh*16, lane), bh[mh]);
#pragma unroll
            for (int ct = 0; ct < 2; ++ct)
#pragma unroll
                for (int mt = 0; mt < 4; ++mt)
                    mmaf16(pacc[ct][mt], va[ct], &bh[mt>>1][(mt&1)*2]);
        }

        CP_WAIT0;
        __syncthreads();
    }

    // ---- sumexp reduce ----
#pragma unroll
    for (int c = 0; c < 2; ++c){
        float v = se[c];
        v += __shfl_xor_sync(0xffffffffu, v, 4);
        v += __shfl_xor_sync(0xffffffffu, v, 8);
        v += __shfl_xor_sync(0xffffffffu, v, 16);
        if (g == 0) atomicAdd(smf + SM_SE/4 + mcol + c, v);
    }
    __syncthreads();
    if (tid < 32) smf[SM_INV/4 + tid] = 1.f / smf[SM_SE/4 + tid];
    __syncthreads();

    // ---- writeout ----
#pragma unroll
    for (int ct = 0; ct < 2; ++ct){
        int c = wid*32 + ct*16 + g;
        float* po0 = out + ((size_t)(b*CVAL + c))*MQ + m0;
        float* po1 = po0 + 8*MQ;
#pragma unroll
        for (int mt = 0; mt < 4; ++mt){
            int m = mt*8 + tg*2;
            float i0 = smf[SM_INV/4 + m], i1 = smf[SM_INV/4 + m + 1];
            float2 o0 = { pacc[ct][mt][0]*i0, pacc[ct][mt][1]*i1 };
            float2 o1 = { pacc[ct][mt][2]*i0, pacc[ct][mt][3]*i1 };
            *(float2*)(po0 + m) = o0;
            *(float2*)(po1 + m) = o1;
        }
    }
}

extern "C" void kernel_launch(void* const* d_in, const int* in_sizes, int n_in,
                              void* d_out, int out_size){
    const float* mk = (const float*)d_in[0];
    const float* qk = (const float*)d_in[1];
    const float* mv = (const float*)d_in[2];
    float* out = (float*)d_out;

    kprep<<<(BB*NKEY + 255)/256, 256>>>(mk);
    qprep<<<(BB*CK*MQ + 255)/256, 256>>>(qk);
    qsqk<<<(BB*MQ + 255)/256, 256>>>(qk);
    vprep<<<(int)(((size_t)BB*CVAL*NKEY/4 + 255)/256), 256>>>(mv);

    cudaFuncSetAttribute(mr_hmma, cudaFuncAttributeMaxDynamicSharedMemorySize, SMEM_BYTES);
    dim3 grid(MQ/BM, BB);
    mr_hmma<<<grid, NT, SMEM_BYTES>>>(out);
}

// round 11
// speedup vs baseline: 1.3521x; 1.0826x over previous
#include <cuda_runtime.h>
#include <cuda_fp16.h>
#include <cstdint>

#define BB 4
#define CK 64
#define NKEY 8192
#define MQ 1024
#define CVAL 512
#define BM 32
#define CHUNK 64
#define NCH (NKEY/CHUNK)
#define NT 512
#define SHIFT 10.0f

__device__ __half g_kth[(size_t)BB*NKEY*CK];   // [b][n][c] hi
__device__ __half g_ktl[(size_t)BB*NKEY*CK];   // [b][n][c] lo
__device__ __half g_qth[(size_t)BB*CK*MQ];     // [b][c][m] hi
__device__ __half g_qtl[(size_t)BB*CK*MQ];     // [b][c][m] lo
__device__ __half g_vhi[(size_t)BB*CVAL*NKEY]; // [b][c][n] hi
__device__ float  g_asq[BB*NKEY];
__device__ float  g_qsq[BB*MQ];

// smem byte offsets
#define SM_ASQ 0        /* 2*256 */
#define SM_QSQ 512
#define SM_INV 640
#define SM_SE  768
#define SM_QH  1024     /* 64 rows * 80B */
#define SM_QL  6144
#define SM_P0  11264    /* 64 rows * 80B */
#define SM_P1  16384
#define SM_KH  21504    /* 2 * 8192 */
#define SM_KL  37888    /* 2 * 8192 */
#define SM_V   54272    /* 2 * 65536 */
#define SMEM_BYTES (54272 + 131072)

__device__ __forceinline__ uint32_t smem_u32(const void* p){
    uint32_t a;
    asm("{ .reg .u64 t; cvta.to.shared.u64 t, %1; cvt.u32.u64 %0, t; }":"=r"(a):"l"(p));
    return a;
}
__device__ __forceinline__ void cpa16(uint32_t s, const void* g){
    asm volatile("cp.async.cg.shared.global [%0], [%1], 16;"::"r"(s),"l"(g):"memory");
}
#define CP_COMMIT asm volatile("cp.async.commit_group;":::"memory")
#define CP_WAIT0  asm volatile("cp.async.wait_group 0;":::"memory")
#define CP_WAIT1  asm volatile("cp.async.wait_group 1;":::"memory")
#define BARRIER   asm volatile("bar.sync 0, 512;":::"memory")

__device__ __forceinline__ uint32_t swz(uint32_t o){ return o ^ ((o>>3)&0x70); }

__device__ __forceinline__ void ldsm4(uint32_t a, uint32_t* r){
    asm volatile("ldmatrix.sync.aligned.m8n8.x4.shared.b16 {%0,%1,%2,%3}, [%4];"
        :"=r"(r[0]),"=r"(r[1]),"=r"(r[2]),"=r"(r[3]):"r"(a));
}
__device__ __forceinline__ void ldsm4t(uint32_t a, uint32_t* r){
    asm volatile("ldmatrix.sync.aligned.m8n8.x4.trans.shared.b16 {%0,%1,%2,%3}, [%4];"
        :"=r"(r[0]),"=r"(r[1]),"=r"(r[2]),"=r"(r[3]):"r"(a));
}
__device__ __forceinline__ void mmaf16(float* d, const uint32_t* a, const uint32_t* b){
    asm volatile("mma.sync.aligned.m16n8k16.row.col.f32.f16.f16.f32 "
        "{%0,%1,%2,%3},{%4,%5,%6,%7},{%8,%9},{%0,%1,%2,%3};"
        :"+f"(d[0]),"+f"(d[1]),"+f"(d[2]),"+f"(d[3])
        :"r"(a[0]),"r"(a[1]),"r"(a[2]),"r"(a[3]),"r"(b[0]),"r"(b[1]));
}
__device__ __forceinline__ uint32_t a_addr(uint32_t base, int rowbase, int kbyte, int lane){
    int r = rowbase + (lane&7) + ((lane>>3)&1)*8;
    uint32_t off = (uint32_t)(r*128 + kbyte + ((lane>>4)<<4));
    return base + swz(off);
}
__device__ __forceinline__ uint32_t b_addr(uint32_t base, int kbase, int nbase, int lane){
    int kk = kbase + (lane&7) + ((lane>>3)&1)*8;
    int nn = nbase + ((lane>>4)<<3);
    return base + (uint32_t)(kk*80 + nn*2);
}

// ---------------- prep (separate kernels — measured-good) ----------------
__global__ void kprep(const float* __restrict__ mk){
    int i = blockIdx.x*blockDim.x + threadIdx.x;
    if (i >= BB*NKEY) return;
    int b = i>>13, n = i&(NKEY-1);
    const float* p = mk + ((size_t)b*CK)*NKEY + n;
    __half* oh = g_kth + ((size_t)b*NKEY + n)*CK;
    __half* ol = g_ktl + ((size_t)b*NKEY + n)*CK;
    float s = 0.f;
#pragma unroll 8
    for (int c = 0; c < CK; ++c){
        float v = p[(size_t)c*NKEY];
        s = fmaf(v, v, s);
        __half h = __float2half_rn(v);
        oh[c] = h; ol[c] = __float2half_rn(v - __half2float(h));
    }
    g_asq[i] = s;
}
__global__ void qprep(const float* __restrict__ qk){
    int i = blockIdx.x*blockDim.x + threadIdx.x;
    if (i >= BB*CK*MQ) return;
    float v = qk[i];
    __half h = __float2half_rn(v);
    g_qth[i] = h; g_qtl[i] = __float2half_rn(v - __half2float(h));
}
__global__ void qsqk(const float* __restrict__ qk){
    int i = blockIdx.x*blockDim.x + threadIdx.x;
    if (i >= BB*MQ) return;
    int b = i>>10, m = i&(MQ-1);
    float s = 0.f;
#pragma unroll 8
    for (int c = 0; c < CK; ++c){ float v = qk[((size_t)b*CK+c)*MQ + m]; s = fmaf(v,v,s); }
    g_qsq[i] = s;
}
__global__ void vprep(const float* __restrict__ mv){
    size_t base = ((size_t)blockIdx.x*blockDim.x + threadIdx.x)*4;
    if (base >= (size_t)BB*CVAL*NKEY) return;
    float4 v = *(const float4*)(mv + base);
    *(__half2*)(g_vhi+base)   = __halves2half2(__float2half_rn(v.x), __float2half_rn(v.y));
    *(__half2*)(g_vhi+base+2) = __halves2half2(__float2half_rn(v.z), __float2half_rn(v.w));
}

// ---------------- main: warp-specialized ----------------
#define PREFETCH_LOOP(it) do {                                                  \
    if ((it) + 1 < NCH){                                                        \
        int n0v = ((it)+1)*CHUNK; uint32_t vb = (uint32_t)(((it)+1)&1)*65536u;  \
        _Pragma("unroll")                                                       \
        for (int k2 = 0; k2 < 8; ++k2){                                         \
            int i2 = tid + k2*NT, c = i2>>3, sg = i2&7;                         \
            cpa16(sb + SM_V + vb + swz(c*128 + sg*16),                          \
                  g_vhi + ((size_t)b*CVAL + c)*NKEY + n0v + sg*8);              \
        }                                                                       \
    }                                                                           \
    if ((it) + 2 < NCH){                                                        \
        int n0k = ((it)+2)*CHUNK; uint32_t kb2 = (uint32_t)((it)&1)*8192u;      \
        int n = tid>>3, sg = tid&7;                                             \
        size_t ko = ((size_t)b*NKEY + n0k + n)*CK + sg*8;                       \
        cpa16(sb + SM_KH + kb2 + swz(n*128 + sg*16), g_kth + ko);               \
        cpa16(sb + SM_KL + kb2 + swz(n*128 + sg*16), g_ktl + ko);               \
        if (tid < 16) cpa16(sb + SM_ASQ + ((it)&1)*256 + tid*16,                \
                            g_asq + b*NKEY + n0k + tid*4);                      \
    }                                                                           \
    CP_COMMIT;                                                                  \
} while (0)

#define QK_STEP(j) do {                                                         \
    const uint32_t kb = (uint32_t)((j)&1)*8192u;                                \
    const uint32_t KHb = sb + SM_KH + kb, KLb = sb + SM_KL + kb;                \
    const float* ASQb = smf + SM_ASQ/4 + ((j)&1)*64;                            \
    float sacc[2][4] = {{0,0,0,0},{0,0,0,0}};                                   \
    _Pragma("unroll")                                                           \
    for (int ks = 0; ks < 4; ++ks){                                             \
        uint32_t ah[4], al[4];                                                  \
        ldsm4(a_addr(KHb, wn*16, ks*32, lane), ah);                             \
        ldsm4(a_addr(KLb, wn*16, ks*32, lane), al);                             \
        mmaf16(sacc[0], ah, &qh[ks][0]); mmaf16(sacc[1], ah, &qh[ks][2]);       \
        mmaf16(sacc[0], ah, &ql[ks][0]); mmaf16(sacc[1], ah, &ql[ks][2]);       \
        mmaf16(sacc[0], al, &qh[ks][0]); mmaf16(sacc[1], al, &qh[ks][2]);       \
    }                                                                           \
    float as0 = ASQb[wn*16 + g]*0.125f, as1 = ASQb[wn*16 + g + 8]*0.125f;       \
    char* pb = smc + (((j)&1) ? SM_P1 : SM_P0);                                 \
    int r0 = (wn*16 + g)*80 + c0*2, r1 = r0 + 8*80;                             \
    float p00 = __expf(fmaf(sacc[0][0], 0.25f, qc[0] - as0));                   \
    float p01 = __expf(fmaf(sacc[0][1], 0.25f, qc[1] - as0));                   \
    float p10 = __expf(fmaf(sacc[0][2], 0.25f, qc[0] - as1));                   \
    float p11 = __expf(fmaf(sacc[0][3], 0.25f, qc[1] - as1));                   \
    se[0] += p00 + p10; se[1] += p01 + p11;                                     \
    *(__half2*)(pb + r0) = __halves2half2(__float2half_rn(p00), __float2half_rn(p01)); \
    *(__half2*)(pb + r1) = __halves2half2(__float2half_rn(p10), __float2half_rn(p11)); \
    p00 = __expf(fmaf(sacc[1][0], 0.25f, qc[2] - as0));                         \
    p01 = __expf(fmaf(sacc[1][1], 0.25f, qc[3] - as0));                         \
    p10 = __expf(fmaf(sacc[1][2], 0.25f, qc[2] - as1));                         \
    p11 = __expf(fmaf(sacc[1][3], 0.25f, qc[3] - as1));                         \
    se[2] += p00 + p10; se[3] += p01 + p11;                                     \
    *(__half2*)(pb + r0 + 16) = __halves2half2(__float2half_rn(p00), __float2half_rn(p01)); \
    *(__half2*)(pb + r1 + 16) = __halves2half2(__float2half_rn(p10), __float2half_rn(p11)); \
} while (0)

__global__ void __launch_bounds__(NT,1) mr_hmma(float* __restrict__ out){
    extern __shared__ char smc[];
    float* smf = (float*)smc;
    const uint32_t sb = smem_u32(smc);
    const int tid = threadIdx.x, wid = tid>>5, lane = tid&31;
    const int b = blockIdx.y, m0 = blockIdx.x*BM;
    const int g = lane>>2, tg = lane&3;

    if (tid < 32) smf[SM_SE/4 + tid] = 0.f;
    // ---- commit group A: Q hi/lo + qsq + K0 + asq0 ----
    if (tid < 256){
        int c = tid>>2, sg4 = tid&3;
        size_t qo = ((size_t)b*CK + c)*MQ + m0 + sg4*8;
        cpa16(sb + SM_QH + c*80 + sg4*16, g_qth + qo);
        cpa16(sb + SM_QL + c*80 + sg4*16, g_qtl + qo);
        if (tid < 8) cpa16(sb + SM_QSQ + tid*16, g_qsq + b*MQ + m0 + tid*4);
    }
    {
        int n = tid>>3, sg = tid&7;
        size_t ko = ((size_t)b*NKEY + n)*CK + sg*8;
        cpa16(sb + SM_KH + swz(n*128 + sg*16), g_kth + ko);
        cpa16(sb + SM_KL + swz(n*128 + sg*16), g_ktl + ko);
        if (tid < 16) cpa16(sb + SM_ASQ + tid*16, g_asq + b*NKEY + tid*4);
    }
    CP_COMMIT;
    // ---- commit group B: V0 + K1 + asq1 ----
    {
#pragma unroll
        for (int k2 = 0; k2 < 8; ++k2){
            int i2 = tid + k2*NT, c = i2>>3, sg = i2&7;
            cpa16(sb + SM_V + swz(c*128 + sg*16),
                  g_vhi + ((size_t)b*CVAL + c)*NKEY + sg*8);
        }
        int n = tid>>3, sg = tid&7;
        size_t ko = ((size_t)b*NKEY + CHUNK + n)*CK + sg*8;
        cpa16(sb + SM_KH + 8192 + swz(n*128 + sg*16), g_kth + ko);
        cpa16(sb + SM_KL + 8192 + swz(n*128 + sg*16), g_ktl + ko);
        if (tid < 16) cpa16(sb + SM_ASQ + 256 + tid*16, g_asq + b*NKEY + CHUNK + tid*4);
    }
    CP_COMMIT;

    if (wid < 8){
        // ================= PV branch (warps 0-7, 64 c-rows each) =============
        float pacc[4][4][4];
#pragma unroll
        for (int i = 0; i < 4; ++i)
#pragma unroll
            for (int j = 0; j < 4; ++j)
#pragma unroll
                for (int k = 0; k < 4; ++k) pacc[i][j][k] = 0.f;

        CP_WAIT1; BARRIER;          // (QK warps compute P_0 now)
        CP_WAIT0; BARRIER;

        for (int it = 0; it < NCH; ++it){
            PREFETCH_LOOP(it);
            const uint32_t Vb = sb + SM_V + (uint32_t)(it&1)*65536u;
            const uint32_t Pb = sb + ((it&1) ? SM_P1 : SM_P0);
#pragma unroll
            for (int ks = 0; ks < 4; ++ks){
                uint32_t va[4][4], bh[2][4];
#pragma unroll
                for (int ct = 0; ct < 4; ++ct)
                    ldsm4(a_addr(Vb, wid*64 + ct*16, ks*32, lane), va[ct]);
#pragma unroll
                for (int mh = 0; mh < 2; ++mh)
                    ldsm4t(b_addr(Pb, ks*16, mh*16, lane), bh[mh]);
#pragma unroll
                for (int ct = 0; ct < 4; ++ct)
#pragma unroll
                    for (int mt = 0; mt < 4; ++mt)
                        mmaf16(pacc[ct][mt], va[ct], &bh[mt>>1][(mt&1)*2]);
            }
            CP_WAIT0; BARRIER;
        }
        BARRIER;                    // se atomics from QK warps complete
        if (tid < 32) smf[SM_INV/4 + tid] = 1.f / smf[SM_SE/4 + tid];
        BARRIER;
        // writeout
#pragma unroll
        for (int ct = 0; ct < 4; ++ct){
            int c = wid*64 + ct*16 + g;
            float* po0 = out + ((size_t)(b*CVAL + c))*MQ + m0;
            float* po1 = po0 + 8*MQ;
#pragma unroll
            for (int mt = 0; mt < 4; ++mt){
                int m = mt*8 + tg*2;
                float i0 = smf[SM_INV/4 + m], i1 = smf[SM_INV/4 + m + 1];
                float2 o0 = { pacc[ct][mt][0]*i0, pacc[ct][mt][1]*i1 };
                float2 o1 = { pacc[ct][mt][2]*i0, pacc[ct][mt][3]*i1 };
                *(float2*)(po0 + m) = o0;
                *(float2*)(po1 + m) = o1;
            }
        }
    } else {
        // ================= QK branch (warps 8-15) ============================
        const int qw = wid - 8, wn = qw&3, wm8 = qw>>2;
        CP_WAIT1; BARRIER;
        // hoist Q fragments + qsq constants
        uint32_t qh[4][4], ql[4][4];
#pragma unroll
        for (int ks = 0; ks < 4; ++ks){
            ldsm4t(b_addr(sb + SM_QH, ks*16, wm8*16, lane), qh[ks]);
            ldsm4t(b_addr(sb + SM_QL, ks*16, wm8*16, lane), ql[ks]);
        }
        const int c0 = wm8*16 + tg*2;
        float qc[4] = { -smf[SM_QSQ/4 + c0]    *0.125f + SHIFT,
                        -smf[SM_QSQ/4 + c0 + 1]*0.125f + SHIFT,
                        -smf[SM_QSQ/4 + c0 + 8]*0.125f + SHIFT,
                        -smf[SM_QSQ/4 + c0 + 9]*0.125f + SHIFT };
        float se[4] = {0.f, 0.f, 0.f, 0.f};

        QK_STEP(0);                 // P_0 into buf 0
        CP_WAIT0; BARRIER;

        for (int it = 0; it < NCH; ++it){
            PREFETCH_LOOP(it);
            if (it + 1 < NCH) QK_STEP(it + 1);
            CP_WAIT0; BARRIER;
        }
        // sumexp reduce + publish
#pragma unroll
        for (int cc = 0; cc < 4; ++cc){
            float v = se[cc];
            v += __shfl_xor_sync(0xffffffffu, v, 4);
            v += __shfl_xor_sync(0xffffffffu, v, 8);
            v += __shfl_xor_sync(0xffffffffu, v, 16);
            if (g == 0) atomicAdd(smf + SM_SE/4 + c0 + (cc&1) + (cc>>1)*8, v);
        }
        BARRIER; BARRIER;
    }
}

extern "C" void kernel_launch(void* const* d_in, const int* in_sizes, int n_in,
                              void* d_out, int out_size){
    const float* mk = (const float*)d_in[0];
    const float* qk = (const float*)d_in[1];
    const float* mv = (const float*)d_in[2];
    float* out = (float*)d_out;

    kprep<<<(BB*NKEY + 255)/256, 256>>>(mk);
    qprep<<<(BB*CK*MQ + 255)/256, 256>>>(qk);
    qsqk<<<(BB*MQ + 255)/256, 256>>>(qk);
    vprep<<<(int)(((size_t)BB*CVAL*NKEY/4 + 255)/256), 256>>>(mv);

    cudaFuncSetAttribute(mr_hmma, cudaFuncAttributeMaxDynamicSharedMemorySize, SMEM_BYTES);
    dim3 grid(MQ/BM, BB);
    mr_hmma<<<grid, NT, SMEM_BYTES>>>(out);
}

// round 12
// speedup vs baseline: 1.6156x; 1.1949x over previous
#include <cuda_runtime.h>
#include <cuda_fp16.h>
#include <cstdint>

#define BB 4
#define CK 64
#define NKEY 8192
#define MQ 1024
#define CVAL 512
#define BM 32
#define CHUNK 64
#define NCH (NKEY/CHUNK)
#define NT 512
#define SHIFT 10.0f

__device__ __half g_kth[(size_t)BB*NKEY*CK];   // [b][n][c] hi
__device__ __half g_qth[(size_t)BB*CK*MQ];     // [b][c][m] hi
__device__ __half g_qtl[(size_t)BB*CK*MQ];     // [b][c][m] lo
__device__ __half g_vhi[(size_t)BB*CVAL*NKEY]; // [b][c][n] hi
__device__ float  g_asq[BB*NKEY];
__device__ float  g_qsq[BB*MQ];

// smem byte offsets
#define SM_ASQ 0        /* 2*256 */
#define SM_QSQ 512
#define SM_INV 640
#define SM_SE  768
#define SM_QH  1024     /* 64 rows * 80B */
#define SM_QL  6144
#define SM_P0  11264    /* 64 rows * 80B */
#define SM_P1  16384
#define SM_KH  21504    /* 2 * 8192 */
#define SM_V   37888    /* 2 * 65536 */
#define SMEM_BYTES (37888 + 131072)

__device__ __forceinline__ uint32_t smem_u32(const void* p){
    uint32_t a;
    asm("{ .reg .u64 t; cvta.to.shared.u64 t, %1; cvt.u32.u64 %0, t; }":"=r"(a):"l"(p));
    return a;
}
__device__ __forceinline__ void cpa16(uint32_t s, const void* g){
    asm volatile("cp.async.cg.shared.global [%0], [%1], 16;"::"r"(s),"l"(g):"memory");
}
#define CP_COMMIT asm volatile("cp.async.commit_group;":::"memory")
#define CP_WAIT0  asm volatile("cp.async.wait_group 0;":::"memory")
#define CP_WAIT1  asm volatile("cp.async.wait_group 1;":::"memory")
#define BARRIER   asm volatile("bar.sync 0, 512;":::"memory")

__device__ __forceinline__ uint32_t swz(uint32_t o){ return o ^ ((o>>3)&0x70); }

__device__ __forceinline__ void ldsm4(uint32_t a, uint32_t* r){
    asm volatile("ldmatrix.sync.aligned.m8n8.x4.shared.b16 {%0,%1,%2,%3}, [%4];"
        :"=r"(r[0]),"=r"(r[1]),"=r"(r[2]),"=r"(r[3]):"r"(a));
}
__device__ __forceinline__ void ldsm4t(uint32_t a, uint32_t* r){
    asm volatile("ldmatrix.sync.aligned.m8n8.x4.trans.shared.b16 {%0,%1,%2,%3}, [%4];"
        :"=r"(r[0]),"=r"(r[1]),"=r"(r[2]),"=r"(r[3]):"r"(a));
}
__device__ __forceinline__ void mmaf16(float* d, const uint32_t* a, const uint32_t* b){
    asm volatile("mma.sync.aligned.m16n8k16.row.col.f32.f16.f16.f32 "
        "{%0,%1,%2,%3},{%4,%5,%6,%7},{%8,%9},{%0,%1,%2,%3};"
        :"+f"(d[0]),"+f"(d[1]),"+f"(d[2]),"+f"(d[3])
        :"r"(a[0]),"r"(a[1]),"r"(a[2]),"r"(a[3]),"r"(b[0]),"r"(b[1]));
}
__device__ __forceinline__ uint32_t a_addr(uint32_t base, int rowbase, int kbyte, int lane){
    int r = rowbase + (lane&7) + ((lane>>3)&1)*8;
    uint32_t off = (uint32_t)(r*128 + kbyte + ((lane>>4)<<4));
    return base + swz(off);
}
__device__ __forceinline__ uint32_t b_addr(uint32_t base, int kbase, int nbase, int lane){
    int kk = kbase + (lane&7) + ((lane>>3)&1)*8;
    int nn = nbase + ((lane>>4)<<3);
    return base + (uint32_t)(kk*80 + nn*2);
}

// ---------------- fused prep: long-pole blocks FIRST ----------------
#define KP_BLKS 128
#define QS_BLKS 16
#define QP_BLKS 1024
#define VP_BLKS 16384
#define PREP_BLKS (KP_BLKS + QS_BLKS + QP_BLKS + VP_BLKS)

__global__ void prep(const float* __restrict__ mk, const float* __restrict__ qk,
                     const float* __restrict__ mv){
    int blk = blockIdx.x;
    if (blk < KP_BLKS){
        int i = blk*256 + threadIdx.x;
        int b = i>>13, n = i&(NKEY-1);
        const float* p = mk + ((size_t)b*CK)*NKEY + n;
        __half* oh = g_kth + ((size_t)b*NKEY + n)*CK;
        float s = 0.f;
#pragma unroll 8
        for (int c = 0; c < CK; ++c){
            float v = p[(size_t)c*NKEY];
            s = fmaf(v, v, s);
            oh[c] = __float2half_rn(v);
        }
        g_asq[i] = s;
        return;
    }
    blk -= KP_BLKS;
    if (blk < QS_BLKS){
        int i = blk*256 + threadIdx.x;
        int b = i>>10, m = i&(MQ-1);
        float s = 0.f;
#pragma unroll 8
        for (int c = 0; c < CK; ++c){ float v = qk[((size_t)b*CK+c)*MQ + m]; s = fmaf(v,v,s); }
        g_qsq[i] = s;
        return;
    }
    blk -= QS_BLKS;
    if (blk < QP_BLKS){
        int i = blk*256 + threadIdx.x;
        float v = qk[i];
        __half h = __float2half_rn(v);
        g_qth[i] = h; g_qtl[i] = __float2half_rn(v - __half2float(h));
        return;
    }
    blk -= QP_BLKS;
    {
        size_t base = ((size_t)blk*256 + threadIdx.x)*4;
        float4 v = *(const float4*)(mv + base);
        *(__half2*)(g_vhi+base)   = __halves2half2(__float2half_rn(v.x), __float2half_rn(v.y));
        *(__half2*)(g_vhi+base+2) = __halves2half2(__float2half_rn(v.z), __float2half_rn(v.w));
    }
}

// ---------------- main: warp-specialized, 2-pass QK ----------------
#define PREFETCH_LOOP(it) do {                                                  \
    if ((it) + 1 < NCH){                                                        \
        int n0v = ((it)+1)*CHUNK; uint32_t vb = (uint32_t)(((it)+1)&1)*65536u;  \
        _Pragma("unroll")                                                       \
        for (int k2 = 0; k2 < 8; ++k2){                                         \
            int i2 = tid + k2*NT, c = i2>>3, sg = i2&7;                         \
            cpa16(sb + SM_V + vb + swz(c*128 + sg*16),                          \
                  g_vhi + ((size_t)b*CVAL + c)*NKEY + n0v + sg*8);              \
        }                                                                       \
    }                                                                           \
    if ((it) + 2 < NCH){                                                        \
        int n0k = ((it)+2)*CHUNK; uint32_t kb2 = (uint32_t)((it)&1)*8192u;      \
        int n = tid>>3, sg = tid&7;                                             \
        size_t ko = ((size_t)b*NKEY + n0k + n)*CK + sg*8;                       \
        cpa16(sb + SM_KH + kb2 + swz(n*128 + sg*16), g_kth + ko);               \
        if (tid < 16) cpa16(sb + SM_ASQ + ((it)&1)*256 + tid*16,                \
                            g_asq + b*NKEY + n0k + tid*4);                      \
    }                                                                           \
    CP_COMMIT;                                                                  \
} while (0)

#define QK_STEP(j) do {                                                         \
    const uint32_t KHb = sb + SM_KH + (uint32_t)((j)&1)*8192u;                  \
    const float* ASQb = smf + SM_ASQ/4 + ((j)&1)*64;                            \
    float sacc[2][4] = {{0,0,0,0},{0,0,0,0}};                                   \
    _Pragma("unroll")                                                           \
    for (int ks = 0; ks < 4; ++ks){                                             \
        uint32_t ah[4];                                                         \
        ldsm4(a_addr(KHb, wn*16, ks*32, lane), ah);                             \
        mmaf16(sacc[0], ah, &qh[ks][0]); mmaf16(sacc[1], ah, &qh[ks][2]);       \
        mmaf16(sacc[0], ah, &ql[ks][0]); mmaf16(sacc[1], ah, &ql[ks][2]);       \
    }                                                                           \
    float as0 = ASQb[wn*16 + g]*0.125f, as1 = ASQb[wn*16 + g + 8]*0.125f;       \
    char* pb = smc + (((j)&1) ? SM_P1 : SM_P0);                                 \
    int r0 = (wn*16 + g)*80 + c0*2, r1 = r0 + 8*80;                             \
    float p00 = __expf(fmaf(sacc[0][0], 0.25f, qc[0] - as0));                   \
    float p01 = __expf(fmaf(sacc[0][1], 0.25f, qc[1] - as0));                   \
    float p10 = __expf(fmaf(sacc[0][2], 0.25f, qc[0] - as1));                   \
    float p11 = __expf(fmaf(sacc[0][3], 0.25f, qc[1] - as1));                   \
    se[0] += p00 + p10; se[1] += p01 + p11;                                     \
    *(__half2*)(pb + r0) = __halves2half2(__float2half_rn(p00), __float2half_rn(p01)); \
    *(__half2*)(pb + r1) = __halves2half2(__float2half_rn(p10), __float2half_rn(p11)); \
    p00 = __expf(fmaf(sacc[1][0], 0.25f, qc[2] - as0));                         \
    p01 = __expf(fmaf(sacc[1][1], 0.25f, qc[3] - as0));                         \
    p10 = __expf(fmaf(sacc[1][2], 0.25f, qc[2] - as1));                         \
    p11 = __expf(fmaf(sacc[1][3], 0.25f, qc[3] - as1));                         \
    se[2] += p00 + p10; se[3] += p01 + p11;                                     \
    *(__half2*)(pb + r0 + 16) = __halves2half2(__float2half_rn(p00), __float2half_rn(p01)); \
    *(__half2*)(pb + r1 + 16) = __halves2half2(__float2half_rn(p10), __float2half_rn(p11)); \
} while (0)

__global__ void __launch_bounds__(NT,1) mr_hmma(float* __restrict__ out){
    extern __shared__ char smc[];
    float* smf = (float*)smc;
    const uint32_t sb = smem_u32(smc);
    const int tid = threadIdx.x, wid = tid>>5, lane = tid&31;
    const int b = blockIdx.y, m0 = blockIdx.x*BM;
    const int g = lane>>2, tg = lane&3;

    if (tid < 32) smf[SM_SE/4 + tid] = 0.f;
    // ---- commit group A: Q hi/lo + qsq + K0 + asq0 ----
    if (tid < 256){
        int c = tid>>2, sg4 = tid&3;
        size_t qo = ((size_t)b*CK + c)*MQ + m0 + sg4*8;
        cpa16(sb + SM_QH + c*80 + sg4*16, g_qth + qo);
        cpa16(sb + SM_QL + c*80 + sg4*16, g_qtl + qo);
        if (tid < 8) cpa16(sb + SM_QSQ + tid*16, g_qsq + b*MQ + m0 + tid*4);
    }
    {
        int n = tid>>3, sg = tid&7;
        size_t ko = ((size_t)b*NKEY + n)*CK + sg*8;
        cpa16(sb + SM_KH + swz(n*128 + sg*16), g_kth + ko);
        if (tid < 16) cpa16(sb + SM_ASQ + tid*16, g_asq + b*NKEY + tid*4);
    }
    CP_COMMIT;
    // ---- commit group B: V0 + K1 + asq1 ----
    {
#pragma unroll
        for (int k2 = 0; k2 < 8; ++k2){
            int i2 = tid + k2*NT, c = i2>>3, sg = i2&7;
            cpa16(sb + SM_V + swz(c*128 + sg*16),
                  g_vhi + ((size_t)b*CVAL + c)*NKEY + sg*8);
        }
        int n = tid>>3, sg = tid&7;
        size_t ko = ((size_t)b*NKEY + CHUNK + n)*CK + sg*8;
        cpa16(sb + SM_KH + 8192 + swz(n*128 + sg*16), g_kth + ko);
        if (tid < 16) cpa16(sb + SM_ASQ + 256 + tid*16, g_asq + b*NKEY + CHUNK + tid*4);
    }
    CP_COMMIT;

    if (wid < 8){
        // ================= PV branch (warps 0-7, 64 c-rows each) =============
        float pacc[4][4][4];
#pragma unroll
        for (int i = 0; i < 4; ++i)
#pragma unroll
            for (int j = 0; j < 4; ++j)
#pragma unroll
                for (int k = 0; k < 4; ++k) pacc[i][j][k] = 0.f;

        CP_WAIT1; BARRIER;          // (QK warps compute P_0 now)
        CP_WAIT0; BARRIER;

        for (int it = 0; it < NCH; ++it){
            PREFETCH_LOOP(it);
            const uint32_t Vb = sb + SM_V + (uint32_t)(it&1)*65536u;
            const uint32_t Pb = sb + ((it&1) ? SM_P1 : SM_P0);
#pragma unroll
            for (int ks = 0; ks < 4; ++ks){
                uint32_t va[4][4], bh[2][4];
#pragma unroll
                for (int ct = 0; ct < 4; ++ct)
                    ldsm4(a_addr(Vb, wid*64 + ct*16, ks*32, lane), va[ct]);
#pragma unroll
                for (int mh = 0; mh < 2; ++mh)
                    ldsm4t(b_addr(Pb, ks*16, mh*16, lane), bh[mh]);
#pragma unroll
                for (int ct = 0; ct < 4; ++ct)
#pragma unroll
                    for (int mt = 0; mt < 4; ++mt)
                        mmaf16(pacc[ct][mt], va[ct], &bh[mt>>1][(mt&1)*2]);
            }
            CP_WAIT0; BARRIER;
        }
        BARRIER;                    // se atomics from QK warps complete
        if (tid < 32) smf[SM_INV/4 + tid] = 1.f / smf[SM_SE/4 + tid];
        BARRIER;
        // writeout
#pragma unroll
        for (int ct = 0; ct < 4; ++ct){
            int c = wid*64 + ct*16 + g;
            float* po0 = out + ((size_t)(b*CVAL + c))*MQ + m0;
            float* po1 = po0 + 8*MQ;
#pragma unroll
            for (int mt = 0; mt < 4; ++mt){
                int m = mt*8 + tg*2;
                float i0 = smf[SM_INV/4 + m], i1 = smf[SM_INV/4 + m + 1];
                float2 o0 = { pacc[ct][mt][0]*i0, pacc[ct][mt][1]*i1 };
                float2 o1 = { pacc[ct][mt][2]*i0, pacc[ct][mt][3]*i1 };
                *(float2*)(po0 + m) = o0;
                *(float2*)(po1 + m) = o1;
            }
        }
    } else {
        // ================= QK branch (warps 8-15) ============================
        const int qw = wid - 8, wn = qw&3, wm8 = qw>>2;
        CP_WAIT1; BARRIER;
        // hoist Q fragments + qsq constants
        uint32_t qh[4][4], ql[4][4];
#pragma unroll
        for (int ks = 0; ks < 4; ++ks){
            ldsm4t(b_addr(sb + SM_QH, ks*16, wm8*16, lane), qh[ks]);
            ldsm4t(b_addr(sb + SM_QL, ks*16, wm8*16, lane), ql[ks]);
        }
        const int c0 = wm8*16 + tg*2;
        float qc[4] = { -smf[SM_QSQ/4 + c0]    *0.125f + SHIFT,
                        -smf[SM_QSQ/4 + c0 + 1]*0.125f + SHIFT,
                        -smf[SM_QSQ/4 + c0 + 8]*0.125f + SHIFT,
                        -smf[SM_QSQ/4 + c0 + 9]*0.125f + SHIFT };
        float se[4] = {0.f, 0.f, 0.f, 0.f};

        QK_STEP(0);                 // P_0 into buf 0
        CP_WAIT0; BARRIER;

        for (int it = 0; it < NCH; ++it){
            PREFETCH_LOOP(it);
            if (it + 1 < NCH) QK_STEP(it + 1);
            CP_WAIT0; BARRIER;
        }
        // sumexp reduce + publish
#pragma unroll
        for (int cc = 0; cc < 4; ++cc){
            float v = se[cc];
            v += __shfl_xor_sync(0xffffffffu, v, 4);
            v += __shfl_xor_sync(0xffffffffu, v, 8);
            v += __shfl_xor_sync(0xffffffffu, v, 16);
            if (g == 0) atomicAdd(smf + SM_SE/4 + c0 + (cc&1) + (cc>>1)*8, v);
        }
        BARRIER; BARRIER;
    }
}

extern "C" void kernel_launch(void* const* d_in, const int* in_sizes, int n_in,
                              void* d_out, int out_size){
    const float* mk = (const float*)d_in[0];
    const float* qk = (const float*)d_in[1];
    const float* mv = (const float*)d_in[2];
    float* out = (float*)d_out;

    prep<<<PREP_BLKS, 256>>>(mk, qk, mv);

    cudaFuncSetAttribute(mr_hmma, cudaFuncAttributeMaxDynamicSharedMemorySize, SMEM_BYTES);
    dim3 grid(MQ/BM, BB);
    mr_hmma<<<grid, NT, SMEM_BYTES>>>(out);
}

// round 13
// speedup vs baseline: 1.7238x; 1.0670x over previous
#include <cuda_runtime.h>
#include <cuda_fp16.h>
#include <cstdint>

#define BB 4
#define CK 64
#define NKEY 8192
#define MQ 1024
#define CVAL 512
#define BM 32
#define CHUNK 64
#define NCH (NKEY/CHUNK)
#define NT 512
#define SHIFT 10.0f

__device__ __half g_kth[(size_t)BB*NKEY*CK];   // [b][n][c] hi
__device__ __half g_qth[(size_t)BB*CK*MQ];     // [b][c][m] hi
__device__ __half g_qtl[(size_t)BB*CK*MQ];     // [b][c][m] lo
__device__ __half g_vhi[(size_t)BB*CVAL*NKEY]; // [b][c][n] hi
__device__ float  g_asq[BB*NKEY];
__device__ float  g_qsq[BB*MQ];

// smem byte offsets
#define SM_ASQ 0        /* 2*256 */
#define SM_QSQ 512
#define SM_INV 640
#define SM_SE  768
#define SM_QH  1024     /* 64 rows * 80B */
#define SM_QL  6144
#define SM_P0  11264    /* 64 rows * 80B */
#define SM_P1  16384
#define SM_KH  21504    /* 2 * 8192 */
#define SM_V   37888    /* 2 * 65536 */
#define SMEM_BYTES (37888 + 131072)

__device__ __forceinline__ uint32_t smem_u32(const void* p){
    uint32_t a;
    asm("{ .reg .u64 t; cvta.to.shared.u64 t, %1; cvt.u32.u64 %0, t; }":"=r"(a):"l"(p));
    return a;
}
__device__ __forceinline__ void cpa16(uint32_t s, const void* g){
    asm volatile("cp.async.cg.shared.global [%0], [%1], 16;"::"r"(s),"l"(g):"memory");
}
#define CP_COMMIT asm volatile("cp.async.commit_group;":::"memory")
#define CP_WAIT0  asm volatile("cp.async.wait_group 0;":::"memory")
#define CP_WAIT1  asm volatile("cp.async.wait_group 1;":::"memory")
#define BARRIER   asm volatile("bar.sync 0, 512;":::"memory")

__device__ __forceinline__ uint32_t swz(uint32_t o){ return o ^ ((o>>3)&0x70); }

__device__ __forceinline__ void ldsm4(uint32_t a, uint32_t* r){
    asm volatile("ldmatrix.sync.aligned.m8n8.x4.shared.b16 {%0,%1,%2,%3}, [%4];"
        :"=r"(r[0]),"=r"(r[1]),"=r"(r[2]),"=r"(r[3]):"r"(a));
}
__device__ __forceinline__ void ldsm4t(uint32_t a, uint32_t* r){
    asm volatile("ldmatrix.sync.aligned.m8n8.x4.trans.shared.b16 {%0,%1,%2,%3}, [%4];"
        :"=r"(r[0]),"=r"(r[1]),"=r"(r[2]),"=r"(r[3]):"r"(a));
}
__device__ __forceinline__ void mmaf16(float* d, const uint32_t* a, const uint32_t* b){
    asm volatile("mma.sync.aligned.m16n8k16.row.col.f32.f16.f16.f32 "
        "{%0,%1,%2,%3},{%4,%5,%6,%7},{%8,%9},{%0,%1,%2,%3};"
        :"+f"(d[0]),"+f"(d[1]),"+f"(d[2]),"+f"(d[3])
        :"r"(a[0]),"r"(a[1]),"r"(a[2]),"r"(a[3]),"r"(b[0]),"r"(b[1]));
}
__device__ __forceinline__ uint32_t a_addr(uint32_t base, int rowbase, int kbyte, int lane){
    int r = rowbase + (lane&7) + ((lane>>3)&1)*8;
    uint32_t off = (uint32_t)(r*128 + kbyte + ((lane>>4)<<4));
    return base + swz(off);
}
__device__ __forceinline__ uint32_t b_addr(uint32_t base, int kbase, int nbase, int lane){
    int kk = kbase + (lane&7) + ((lane>>3)&1)*8;
    int nn = nbase + ((lane>>4)<<3);
    return base + (uint32_t)(kk*80 + nn*2);
}

// ---------------- fused prep: long-pole blocks FIRST ----------------
#define KP_BLKS 128
#define QS_BLKS 16
#define QP_BLKS 1024
#define VP_BLKS 16384
#define PREP_BLKS (KP_BLKS + QS_BLKS + QP_BLKS + VP_BLKS)

__global__ void prep(const float* __restrict__ mk, const float* __restrict__ qk,
                     const float* __restrict__ mv){
    int blk = blockIdx.x;
    if (blk < KP_BLKS){
        int i = blk*256 + threadIdx.x;
        int b = i>>13, n = i&(NKEY-1);
        const float* p = mk + ((size_t)b*CK)*NKEY + n;
        __half* oh = g_kth + ((size_t)b*NKEY + n)*CK;
        float s = 0.f;
#pragma unroll 8
        for (int c = 0; c < CK; ++c){
            float v = p[(size_t)c*NKEY];
            s = fmaf(v, v, s);
            oh[c] = __float2half_rn(v);
        }
        g_asq[i] = s;
        return;
    }
    blk -= KP_BLKS;
    if (blk < QS_BLKS){
        int i = blk*256 + threadIdx.x;
        int b = i>>10, m = i&(MQ-1);
        float s = 0.f;
#pragma unroll 8
        for (int c = 0; c < CK; ++c){ float v = qk[((size_t)b*CK+c)*MQ + m]; s = fmaf(v,v,s); }
        g_qsq[i] = s;
        return;
    }
    blk -= QS_BLKS;
    if (blk < QP_BLKS){
        int i = blk*256 + threadIdx.x;
        float v = qk[i];
        __half h = __float2half_rn(v);
        g_qth[i] = h; g_qtl[i] = __float2half_rn(v - __half2float(h));
        return;
    }
    blk -= QP_BLKS;
    {
        size_t base = ((size_t)blk*256 + threadIdx.x)*4;
        float4 v = *(const float4*)(mv + base);
        *(__half2*)(g_vhi+base)   = __halves2half2(__float2half_rn(v.x), __float2half_rn(v.y));
        *(__half2*)(g_vhi+base+2) = __halves2half2(__float2half_rn(v.z), __float2half_rn(v.w));
    }
}

// ---------------- main: warp-specialized, PV-side staging ----------------
#define QK_STEP(j) do {                                                         \
    const uint32_t KHb = sb + SM_KH + (uint32_t)((j)&1)*8192u;                  \
    const float* ASQb = smf + SM_ASQ/4 + ((j)&1)*64;                            \
    float sacc[2][4] = {{0,0,0,0},{0,0,0,0}};                                   \
    _Pragma("unroll")                                                           \
    for (int ks = 0; ks < 4; ++ks){                                             \
        uint32_t ah[4];                                                         \
        ldsm4(a_addr(KHb, wn*16, ks*32, lane), ah);                             \
        mmaf16(sacc[0], ah, &qh[ks][0]); mmaf16(sacc[1], ah, &qh[ks][2]);       \
        mmaf16(sacc[0], ah, &ql[ks][0]); mmaf16(sacc[1], ah, &ql[ks][2]);       \
    }                                                                           \
    float as0 = ASQb[wn*16 + g]*0.125f, as1 = ASQb[wn*16 + g + 8]*0.125f;       \
    char* pb = smc + (((j)&1) ? SM_P1 : SM_P0);                                 \
    int r0 = (wn*16 + g)*80 + c0*2, r1 = r0 + 8*80;                             \
    float p00 = __expf(fmaf(sacc[0][0], 0.25f, qc[0] - as0));                   \
    float p01 = __expf(fmaf(sacc[0][1], 0.25f, qc[1] - as0));                   \
    float p10 = __expf(fmaf(sacc[0][2], 0.25f, qc[0] - as1));                   \
    float p11 = __expf(fmaf(sacc[0][3], 0.25f, qc[1] - as1));                   \
    se[0] += p00 + p10; se[1] += p01 + p11;                                     \
    *(__half2*)(pb + r0) = __halves2half2(__float2half_rn(p00), __float2half_rn(p01)); \
    *(__half2*)(pb + r1) = __halves2half2(__float2half_rn(p10), __float2half_rn(p11)); \
    p00 = __expf(fmaf(sacc[1][0], 0.25f, qc[2] - as0));                         \
    p01 = __expf(fmaf(sacc[1][1], 0.25f, qc[3] - as0));                         \
    p10 = __expf(fmaf(sacc[1][2], 0.25f, qc[2] - as1));                         \
    p11 = __expf(fmaf(sacc[1][3], 0.25f, qc[3] - as1));                         \
    se[2] += p00 + p10; se[3] += p01 + p11;                                     \
    *(__half2*)(pb + r0 + 16) = __halves2half2(__float2half_rn(p00), __float2half_rn(p01)); \
    *(__half2*)(pb + r1 + 16) = __halves2half2(__float2half_rn(p10), __float2half_rn(p11)); \
} while (0)

__global__ void __launch_bounds__(NT,1) mr_hmma(float* __restrict__ out){
    extern __shared__ char smc[];
    float* smf = (float*)smc;
    const uint32_t sb = smem_u32(smc);
    const int tid = threadIdx.x, wid = tid>>5, lane = tid&31;
    const int b = blockIdx.y, m0 = blockIdx.x*BM;
    const int g = lane>>2, tg = lane&3;

    if (tid < 32) smf[SM_SE/4 + tid] = 0.f;
    // ---- commit group A: Q hi/lo + qsq + K0 + asq0 (all threads) ----
    if (tid < 256){
        int c = tid>>2, sg4 = tid&3;
        size_t qo = ((size_t)b*CK + c)*MQ + m0 + sg4*8;
        cpa16(sb + SM_QH + c*80 + sg4*16, g_qth + qo);
        cpa16(sb + SM_QL + c*80 + sg4*16, g_qtl + qo);
        if (tid < 8) cpa16(sb + SM_QSQ + tid*16, g_qsq + b*MQ + m0 + tid*4);
    }
    {
        int n = tid>>3, sg = tid&7;
        size_t ko = ((size_t)b*NKEY + n)*CK + sg*8;
        cpa16(sb + SM_KH + swz(n*128 + sg*16), g_kth + ko);
        if (tid < 16) cpa16(sb + SM_ASQ + tid*16, g_asq + b*NKEY + tid*4);
    }
    CP_COMMIT;
    // ---- commit group B: V0 + K1 + asq1 (all threads) ----
    {
#pragma unroll
        for (int k2 = 0; k2 < 8; ++k2){
            int i2 = tid + k2*NT, c = i2>>3, sg = i2&7;
            cpa16(sb + SM_V + swz(c*128 + sg*16),
                  g_vhi + ((size_t)b*CVAL + c)*NKEY + sg*8);
        }
        int n = tid>>3, sg = tid&7;
        size_t ko = ((size_t)b*NKEY + CHUNK + n)*CK + sg*8;
        cpa16(sb + SM_KH + 8192 + swz(n*128 + sg*16), g_kth + ko);
        if (tid < 16) cpa16(sb + SM_ASQ + 256 + tid*16, g_asq + b*NKEY + CHUNK + tid*4);
    }
    CP_COMMIT;

    if (wid < 8){
        // ========== PV branch (warps 0-7): all staging + PV MMAs ==========
        // hoisted prefetch bases (per-thread invariant)
        const int pc0 = tid>>3, psg = tid&7;
        const __half* vsrc = g_vhi + ((size_t)b*CVAL + pc0)*NKEY + psg*8;
        const uint32_t vdst = sb + SM_V + swz((uint32_t)(pc0*128 + psg*16));
        const __half* ksrc = g_kth + ((size_t)b*NKEY + pc0)*CK + psg*8;
        const uint32_t kdst = sb + SM_KH + swz((uint32_t)(pc0*128 + psg*16));

        float pacc[4][4][4];
#pragma unroll
        for (int i = 0; i < 4; ++i)
#pragma unroll
            for (int j = 0; j < 4; ++j)
#pragma unroll
                for (int k = 0; k < 4; ++k) pacc[i][j][k] = 0.f;

        CP_WAIT1; BARRIER;          // (QK warps compute P_0 now)
        CP_WAIT0; BARRIER;

        for (int it = 0; it < NCH; ++it){
            // prefetch V(it+1) + K(it+2) — PV warps only
            if (it + 1 < NCH){
                const __half* vp = vsrc + (it+1)*CHUNK;
                const uint32_t vb = vdst + (uint32_t)(((it)+1)&1)*65536u;
#pragma unroll
                for (int k2 = 0; k2 < 16; ++k2)
                    cpa16(vb + k2*4096u, vp + (size_t)k2*32*NKEY);
            }
            if (it + 2 < NCH){
                const __half* kp = ksrc + (size_t)(it+2)*CHUNK*CK;
                const uint32_t kb = kdst + (uint32_t)((it)&1)*8192u;
                cpa16(kb, kp);
                cpa16(kb + 4096u, kp + 32*CK);
                if (tid < 16) cpa16(sb + SM_ASQ + ((it)&1)*256 + tid*16,
                                    g_asq + b*NKEY + (it+2)*CHUNK + tid*4);
            }
            CP_COMMIT;

            const uint32_t Vb = sb + SM_V + (uint32_t)(it&1)*65536u;
            const uint32_t Pb = sb + ((it&1) ? SM_P1 : SM_P0);
#pragma unroll
            for (int ks = 0; ks < 4; ++ks){
                uint32_t va[4][4], bh[2][4];
#pragma unroll
                for (int ct = 0; ct < 4; ++ct)
                    ldsm4(a_addr(Vb, wid*64 + ct*16, ks*32, lane), va[ct]);
#pragma unroll
                for (int mh = 0; mh < 2; ++mh)
                    ldsm4t(b_addr(Pb, ks*16, mh*16, lane), bh[mh]);
#pragma unroll
                for (int ct = 0; ct < 4; ++ct)
#pragma unroll
                    for (int mt = 0; mt < 4; ++mt)
                        mmaf16(pacc[ct][mt], va[ct], &bh[mt>>1][(mt&1)*2]);
            }
            CP_WAIT0; BARRIER;
        }
        BARRIER;                    // se atomics from QK warps complete
        if (tid < 32) smf[SM_INV/4 + tid] = 1.f / smf[SM_SE/4 + tid];
        BARRIER;
        // writeout
#pragma unroll
        for (int ct = 0; ct < 4; ++ct){
            int c = wid*64 + ct*16 + g;
            float* po0 = out + ((size_t)(b*CVAL + c))*MQ + m0;
            float* po1 = po0 + 8*MQ;
#pragma unroll
            for (int mt = 0; mt < 4; ++mt){
                int m = mt*8 + tg*2;
                float i0 = smf[SM_INV/4 + m], i1 = smf[SM_INV/4 + m + 1];
                float2 o0 = { pacc[ct][mt][0]*i0, pacc[ct][mt][1]*i1 };
                float2 o1 = { pacc[ct][mt][2]*i0, pacc[ct][mt][3]*i1 };
                *(float2*)(po0 + m) = o0;
                *(float2*)(po1 + m) = o1;
            }
        }
    } else {
        // ========== QK branch (warps 8-15): MMA + softmax only ==========
        const int qw = wid - 8, wn = qw&3, wm8 = qw>>2;
        CP_WAIT1; BARRIER;
        // hoist Q fragments + qsq constants
        uint32_t qh[4][4], ql[4][4];
#pragma unroll
        for (int ks = 0; ks < 4; ++ks){
            ldsm4t(b_addr(sb + SM_QH, ks*16, wm8*16, lane), qh[ks]);
            ldsm4t(b_addr(sb + SM_QL, ks*16, wm8*16, lane), ql[ks]);
        }
        const int c0 = wm8*16 + tg*2;
        float qc[4] = { -smf[SM_QSQ/4 + c0]    *0.125f + SHIFT,
                        -smf[SM_QSQ/4 + c0 + 1]*0.125f + SHIFT,
                        -smf[SM_QSQ/4 + c0 + 8]*0.125f + SHIFT,
                        -smf[SM_QSQ/4 + c0 + 9]*0.125f + SHIFT };
        float se[4] = {0.f, 0.f, 0.f, 0.f};

        QK_STEP(0);                 // P_0 into buf 0
        CP_WAIT0; BARRIER;

        for (int it = 0; it < NCH; ++it){
            if (it + 1 < NCH) QK_STEP(it + 1);
            BARRIER;
        }
        // sumexp reduce + publish
#pragma unroll
        for (int cc = 0; cc < 4; ++cc){
            float v = se[cc];
            v += __shfl_xor_sync(0xffffffffu, v, 4);
            v += __shfl_xor_sync(0xffffffffu, v, 8);
            v += __shfl_xor_sync(0xffffffffu, v, 16);
            if (g == 0) atomicAdd(smf + SM_SE/4 + c0 + (cc&1) + (cc>>1)*8, v);
        }
        BARRIER; BARRIER;
    }
}

extern "C" void kernel_launch(void* const* d_in, const int* in_sizes, int n_in,
                              void* d_out, int out_size){
    const float* mk = (const float*)d_in[0];
    const float* qk = (const float*)d_in[1];
    const float* mv = (const float*)d_in[2];
    float* out = (float*)d_out;

    prep<<<PREP_BLKS, 256>>>(mk, qk, mv);

    cudaFuncSetAttribute(mr_hmma, cudaFuncAttributeMaxDynamicSharedMemorySize, SMEM_BYTES);
    dim3 grid(MQ/BM, BB);
    mr_hmma<<<grid, NT, SMEM_BYTES>>>(out);
}